// round 1
// baseline (speedup 1.0000x reference)
#include <cuda_runtime.h>
#include <cuda_fp16.h>

#define LOG2E_F 1.4426950408889634f
#define LN2_F   0.6931471805599453f

constexpr int NB = 64;       // batch N
constexpr int TT = 256;      // T
constexpr int VV = 32000;    // vocab
constexpr int EE = 256;      // embed dim
constexpr int KC = 128;      // clusters K
constexpr int RR = (TT - 1) * NB;   // 16320 (t,n) rows
constexpr int VTILES = VV / 64;     // 500

// ------- static scratch (allocation-free rule: __device__ globals) -------
__device__ __align__(16) __half d_P[(size_t)RR * KC * KC];   // [r][i][j] transition probs (fp16)
__device__ __align__(16) float  d_EmitAdd[(size_t)RR * KC];  // [r][j]  log p(w_{t+1}|j)
__device__ __align__(16) float  d_LogitsT[(size_t)VV * KC];  // [v][c]  emission logits (transposed)
__device__ float  d_PM[VTILES * KC];
__device__ float  d_PS[VTILES * KC];
__device__ float  d_RowLse[KC];
__device__ float  d_Chain[NB];

__device__ __forceinline__ float warpMax(float v) {
#pragma unroll
    for (int o = 16; o; o >>= 1) v = fmaxf(v, __shfl_xor_sync(0xffffffffu, v, o));
    return v;
}
__device__ __forceinline__ float warpSum(float v) {
#pragma unroll
    for (int o = 16; o; o >>= 1) v += __shfl_xor_sync(0xffffffffu, v, o);
    return v;
}

// =====================================================================
// Phase A: S[r, i*128+j] = embed[x[n,t]] . trans_w[i*128+j]  (K=256)
// fused epilogue: per (r,i) softmax over j -> store fp16 probabilities
// grid = (255 row-tiles of 64, 128 i), block = 256 threads
// thread tile: 8 rows x 4 cols
// =====================================================================
__global__ void __launch_bounds__(256) k_phaseA(const int* __restrict__ x,
                                                const float* __restrict__ embed_w,
                                                const float* __restrict__ trans_w)
{
    const int rt = blockIdx.x;      // 0..254
    const int iC = blockIdx.y;      // 0..127
    __shared__ float exs[16][65];   // [kk][row]
    __shared__ float trs[16][129];  // [kk][j]
    __shared__ int   toks[64];

    const int tid   = threadIdx.x;
    const int lane  = tid & 31;
    const int wg    = tid >> 5;       // 0..7
    const int rbase = wg * 8;
    const int cbase = lane * 4;

    if (tid < 64) {
        int r = rt * 64 + tid;
        int t = r >> 6, n = r & 63;
        toks[tid] = x[n * TT + t];
    }
    __syncthreads();

    float acc[8][4];
#pragma unroll
    for (int a = 0; a < 8; a++)
#pragma unroll
        for (int b = 0; b < 4; b++) acc[a][b] = 0.0f;

    const size_t trow = (size_t)iC * 128 * EE;

    for (int k0 = 0; k0 < EE; k0 += 16) {
        // ex chunk: 64 rows x 16k  (1024 elems, 4 per thread)
#pragma unroll
        for (int it = 0; it < 4; it++) {
            int u = tid + it * 256;
            int kk = u & 15, row = u >> 4;
            exs[kk][row] = embed_w[(size_t)toks[row] * EE + k0 + kk];
        }
        // trans chunk: 128 j x 16k (2048 elems, 8 per thread)
#pragma unroll
        for (int it = 0; it < 8; it++) {
            int u = tid + it * 256;
            int kk = u & 15, j = u >> 4;
            trs[kk][j] = trans_w[trow + (size_t)j * EE + k0 + kk];
        }
        __syncthreads();
#pragma unroll
        for (int kk = 0; kk < 16; kk++) {
            float av[8], bv[4];
#pragma unroll
            for (int r2 = 0; r2 < 8; r2++) av[r2] = exs[kk][rbase + r2];
#pragma unroll
            for (int c2 = 0; c2 < 4; c2++) bv[c2] = trs[kk][cbase + c2];
#pragma unroll
            for (int r2 = 0; r2 < 8; r2++)
#pragma unroll
                for (int c2 = 0; c2 < 4; c2++)
                    acc[r2][c2] = fmaf(av[r2], bv[c2], acc[r2][c2]);
        }
        __syncthreads();
    }

    // epilogue: warp `wg` owns rows rbase..rbase+7, each full 128-j row lives in this warp
#pragma unroll
    for (int r2 = 0; r2 < 8; r2++) {
        float m = fmaxf(fmaxf(acc[r2][0], acc[r2][1]), fmaxf(acc[r2][2], acc[r2][3]));
        m = warpMax(m);
        float e0 = exp2f((acc[r2][0] - m) * LOG2E_F);
        float e1 = exp2f((acc[r2][1] - m) * LOG2E_F);
        float e2 = exp2f((acc[r2][2] - m) * LOG2E_F);
        float e3 = exp2f((acc[r2][3] - m) * LOG2E_F);
        float s = warpSum(e0 + e1 + e2 + e3);
        float inv = 1.0f / s;
        int r = rt * 64 + rbase + r2;
        size_t base = (((size_t)r * KC) + iC) * KC + cbase;
        union { uint2 u; __half2 h[2]; } pk;
        pk.h[0] = __floats2half2_rn(e0 * inv, e1 * inv);
        pk.h[1] = __floats2half2_rn(e2 * inv, e3 * inv);
        *reinterpret_cast<uint2*>(&d_P[base]) = pk.u;
    }
}

// =====================================================================
// Emission logits GEMM: logitsT[v][c] = emit_w[v] . emb_cluster_w[c] (K=128)
// + per-block partial (max,sumexp) over v for each c
// grid = 500 v-tiles of 64, block = 256
// =====================================================================
__global__ void __launch_bounds__(256) k_emit_gemm(const float* __restrict__ emit_w,
                                                   const float* __restrict__ emb_cluster_w)
{
    const int vt = blockIdx.x;
    __shared__ float avs[16][65];
    __shared__ float bvs[16][129];
    __shared__ float pmS[8][128];
    __shared__ float psS[8][128];

    const int tid   = threadIdx.x;
    const int lane  = tid & 31;
    const int wg    = tid >> 5;
    const int rbase = wg * 8;
    const int cbase = lane * 4;

    float acc[8][4];
#pragma unroll
    for (int a = 0; a < 8; a++)
#pragma unroll
        for (int b = 0; b < 4; b++) acc[a][b] = 0.0f;

    for (int k0 = 0; k0 < KC; k0 += 16) {
#pragma unroll
        for (int it = 0; it < 4; it++) {
            int u = tid + it * 256;
            int kk = u & 15, row = u >> 4;
            avs[kk][row] = emit_w[(size_t)(vt * 64 + row) * KC + k0 + kk];
        }
#pragma unroll
        for (int it = 0; it < 8; it++) {
            int u = tid + it * 256;
            int kk = u & 15, c = u >> 4;
            bvs[kk][c] = emb_cluster_w[(size_t)c * KC + k0 + kk];
        }
        __syncthreads();
#pragma unroll
        for (int kk = 0; kk < 16; kk++) {
            float av[8], bv[4];
#pragma unroll
            for (int r2 = 0; r2 < 8; r2++) av[r2] = avs[kk][rbase + r2];
#pragma unroll
            for (int c2 = 0; c2 < 4; c2++) bv[c2] = bvs[kk][cbase + c2];
#pragma unroll
            for (int r2 = 0; r2 < 8; r2++)
#pragma unroll
                for (int c2 = 0; c2 < 4; c2++)
                    acc[r2][c2] = fmaf(av[r2], bv[c2], acc[r2][c2]);
        }
        __syncthreads();
    }

    // store logits + per-thread partial lse over its 8 rows
    float pm[4], ps[4];
#pragma unroll
    for (int c2 = 0; c2 < 4; c2++) { pm[c2] = -3.4e38f; ps[c2] = 0.0f; }
#pragma unroll
    for (int r2 = 0; r2 < 8; r2++) {
        int v = vt * 64 + rbase + r2;
        float4 f4 = make_float4(acc[r2][0], acc[r2][1], acc[r2][2], acc[r2][3]);
        *reinterpret_cast<float4*>(&d_LogitsT[(size_t)v * KC + cbase]) = f4;
#pragma unroll
        for (int c2 = 0; c2 < 4; c2++) pm[c2] = fmaxf(pm[c2], acc[r2][c2]);
    }
#pragma unroll
    for (int r2 = 0; r2 < 8; r2++)
#pragma unroll
        for (int c2 = 0; c2 < 4; c2++)
            ps[c2] += exp2f((acc[r2][c2] - pm[c2]) * LOG2E_F);

#pragma unroll
    for (int c2 = 0; c2 < 4; c2++) { pmS[wg][cbase + c2] = pm[c2]; psS[wg][cbase + c2] = ps[c2]; }
    __syncthreads();
    if (tid < 128) {
        float m = pmS[0][tid];
#pragma unroll
        for (int w = 1; w < 8; w++) m = fmaxf(m, pmS[w][tid]);
        float s = 0.0f;
#pragma unroll
        for (int w = 0; w < 8; w++) s += psS[w][tid] * exp2f((pmS[w][tid] - m) * LOG2E_F);
        d_PM[vt * KC + tid] = m;
        d_PS[vt * KC + tid] = s;
    }
}

// combine 500 partial lse per cluster
__global__ void k_lse_final()
{
    int c = threadIdx.x;
    float m = -3.4e38f, s = 0.0f;
    for (int b = 0; b < VTILES; b++) {
        float bm = d_PM[b * KC + c], bs = d_PS[b * KC + c];
        if (bm > m) { s = s * exp2f((m - bm) * LOG2E_F) + bs; m = bm; }
        else        { s += bs * exp2f((bm - m) * LOG2E_F); }
    }
    d_RowLse[c] = m + log2f(s) * LN2_F;
}

// EmitAdd[r][j] = logitsT[x[n,t+1]][j] - RowLse[j]
__global__ void __launch_bounds__(128) k_emit_add(const int* __restrict__ x)
{
    int r = blockIdx.x, j = threadIdx.x;
    int t = r >> 6, n = r & 63;
    int w = x[n * TT + t + 1];
    d_EmitAdd[(size_t)r * KC + j] = d_LogitsT[(size_t)w * KC + j] - d_RowLse[j];
}

// =====================================================================
// Phase B: sequential scan. One block per chain n (independent chains).
// cur_j = m + log( sum_i exp(alpha_i - m) * P[r][i][j] ) + EmitAdd[r][j]
// block: 128 threads = (ic = tid>>5: i-chunk of 32) x (jg = tid&31: 4 cols)
// =====================================================================
__global__ void __launch_bounds__(128) k_scan(const float* __restrict__ start_w,
                                              const float* __restrict__ start_b)
{
    const int n    = blockIdx.x;
    const int tid  = threadIdx.x;
    const int lane = tid & 31;
    const int wid  = tid >> 5;
    const int jg   = lane;          // 4-col group
    const int ic   = wid;           // i chunk
    __shared__ float w_s[128];
    __shared__ float red[4][132];
    __shared__ float smax[4], ssum[4];

    // pre = log_softmax(start_w[:,0] + start_b)
    float a0 = start_w[tid] + start_b[tid];
    float m = warpMax(a0);
    if (lane == 0) smax[wid] = m;
    __syncthreads();
    m = fmaxf(fmaxf(smax[0], smax[1]), fmaxf(smax[2], smax[3]));
    float e = exp2f((a0 - m) * LOG2E_F);
    float s = warpSum(e);
    if (lane == 0) ssum[wid] = s;
    __syncthreads();
    s = ssum[0] + ssum[1] + ssum[2] + ssum[3];
    float alpha = a0 - m - log2f(s) * LN2_F;
    __syncthreads();

    for (int t = 0; t < TT - 1; t++) {
        const int r = t * NB + n;
        float mm = warpMax(alpha);
        if (lane == 0) smax[wid] = mm;
        __syncthreads();
        mm = fmaxf(fmaxf(smax[0], smax[1]), fmaxf(smax[2], smax[3]));
        w_s[tid] = exp2f((alpha - mm) * LOG2E_F);
        __syncthreads();

        const __half* Pp = d_P + (((size_t)r * KC) + ic * 32) * KC + jg * 4;
        float acc0 = 0.f, acc1 = 0.f, acc2 = 0.f, acc3 = 0.f;
#pragma unroll 8
        for (int ii = 0; ii < 32; ii++) {
            uint2 u = *reinterpret_cast<const uint2*>(Pp + (size_t)ii * KC);
            float wi = w_s[ic * 32 + ii];
            __half2 h01 = *reinterpret_cast<__half2*>(&u.x);
            __half2 h23 = *reinterpret_cast<__half2*>(&u.y);
            float2 f01 = __half22float2(h01);
            float2 f23 = __half22float2(h23);
            acc0 = fmaf(wi, f01.x, acc0);
            acc1 = fmaf(wi, f01.y, acc1);
            acc2 = fmaf(wi, f23.x, acc2);
            acc3 = fmaf(wi, f23.y, acc3);
        }
        red[ic][jg * 4 + 0] = acc0;
        red[ic][jg * 4 + 1] = acc1;
        red[ic][jg * 4 + 2] = acc2;
        red[ic][jg * 4 + 3] = acc3;
        __syncthreads();
        float tot = red[0][tid] + red[1][tid] + red[2][tid] + red[3][tid];
        alpha = mm + log2f(tot) * LN2_F + d_EmitAdd[(size_t)r * KC + tid];
        __syncthreads();
    }

    // final lse over clusters
    float mm = warpMax(alpha);
    if (lane == 0) smax[wid] = mm;
    __syncthreads();
    mm = fmaxf(fmaxf(smax[0], smax[1]), fmaxf(smax[2], smax[3]));
    float ee = exp2f((alpha - mm) * LOG2E_F);
    float ss = warpSum(ee);
    if (lane == 0) ssum[wid] = ss;
    __syncthreads();
    if (tid == 0) {
        float stot = ssum[0] + ssum[1] + ssum[2] + ssum[3];
        d_Chain[n] = mm + log2f(stot) * LN2_F;
    }
}

__global__ void k_final(float* out, int out_size)
{
    __shared__ float sh;
    if (threadIdx.x == 0) {
        float s = 0.0f;
        for (int i = 0; i < NB; i++) s += d_Chain[i];
        sh = -s / (float)NB;
    }
    __syncthreads();
    for (int i = threadIdx.x; i < out_size; i += blockDim.x) out[i] = sh;
}

extern "C" void kernel_launch(void* const* d_in, const int* in_sizes, int n_in,
                              void* d_out, int out_size)
{
    (void)in_sizes; (void)n_in;
    const int*   x             = (const int*)d_in[0];
    const float* embed_w       = (const float*)d_in[1];
    const float* trans_w       = (const float*)d_in[2];
    const float* start_w       = (const float*)d_in[3];
    const float* start_b       = (const float*)d_in[4];
    const float* emb_cluster_w = (const float*)d_in[5];
    const float* emit_w        = (const float*)d_in[6];

    k_emit_gemm<<<VTILES, 256>>>(emit_w, emb_cluster_w);
    k_lse_final<<<1, 128>>>();
    k_emit_add<<<RR, 128>>>(x);
    dim3 gA(RR / 64, KC, 1);
    k_phaseA<<<gA, 256>>>(x, embed_w, trans_w);
    k_scan<<<NB, 128>>>(start_w, start_b);
    k_final<<<1, 64>>>((float*)d_out, out_size);
}

// round 3
// speedup vs baseline: 5.2415x; 5.2415x over previous
#include <cuda_runtime.h>
#include <cuda_fp16.h>
#include <cuda_bf16.h>
#include <cstdint>

#define LOG2E_F 1.4426950408889634f
#define LN2_F   0.6931471805599453f

constexpr int NB = 64;       // batch N
constexpr int TT = 256;      // T
constexpr int VV = 32000;    // vocab
constexpr int EE = 256;      // embed dim
constexpr int KC = 128;      // clusters K
constexpr int RR = (TT - 1) * NB;   // 16320 (t,n) rows
constexpr int RPAD = 16384;         // padded rows for MMA tiling
constexpr int VTILES = VV / 64;     // 500

// ------- static scratch (allocation-free rule: __device__ globals) -------
__device__ __align__(16) __half d_P[(size_t)RR * KC * KC];   // [r][i][j] transition probs (fp16)
__device__ __align__(16) float  d_EmitAdd[(size_t)RR * KC];  // [r][j]
__device__ __align__(16) float  d_LogitsT[(size_t)VV * KC];  // [v][c]
__device__ __align__(16) __nv_bfloat16 d_Ab[(size_t)RPAD * EE]; // gathered embeddings bf16
__device__ __align__(16) __nv_bfloat16 d_Bb[(size_t)KC * KC * EE]; // trans_w bf16
__device__ float  d_PM[VTILES * KC];
__device__ float  d_PS[VTILES * KC];
__device__ float  d_RowLse[KC];
__device__ float  d_Chain[NB];

__device__ __forceinline__ uint32_t smem_u32(const void* p) {
    uint32_t a;
    asm("{ .reg .u64 t; cvta.to.shared.u64 t, %1; cvt.u32.u64 %0, t; }" : "=r"(a) : "l"(p));
    return a;
}
__device__ __forceinline__ void cpa16(uint32_t saddr, const void* g) {
    asm volatile("cp.async.cg.shared.global [%0], [%1], 16;" :: "r"(saddr), "l"(g));
}
__device__ __forceinline__ void ldsm_x4(uint32_t& r0, uint32_t& r1, uint32_t& r2, uint32_t& r3,
                                        uint32_t addr) {
    asm volatile("ldmatrix.sync.aligned.m8n8.x4.shared.b16 {%0,%1,%2,%3}, [%4];"
                 : "=r"(r0), "=r"(r1), "=r"(r2), "=r"(r3) : "r"(addr));
}
__device__ __forceinline__ void mma_bf16(float& d0, float& d1, float& d2, float& d3,
                                         uint32_t a0, uint32_t a1, uint32_t a2, uint32_t a3,
                                         uint32_t b0, uint32_t b1) {
    asm volatile("mma.sync.aligned.m16n8k16.row.col.f32.bf16.bf16.f32 "
                 "{%0,%1,%2,%3}, {%4,%5,%6,%7}, {%8,%9}, {%0,%1,%2,%3};"
                 : "+f"(d0), "+f"(d1), "+f"(d2), "+f"(d3)
                 : "r"(a0), "r"(a1), "r"(a2), "r"(a3), "r"(b0), "r"(b1));
}

__device__ __forceinline__ float warpMax(float v) {
#pragma unroll
    for (int o = 16; o; o >>= 1) v = fmaxf(v, __shfl_xor_sync(0xffffffffu, v, o));
    return v;
}
__device__ __forceinline__ float warpSum(float v) {
#pragma unroll
    for (int o = 16; o; o >>= 1) v += __shfl_xor_sync(0xffffffffu, v, o);
    return v;
}

// =====================================================================
// Operand prep
// =====================================================================
__global__ void __launch_bounds__(64) k_prepA(const int* __restrict__ x,
                                              const float* __restrict__ embed_w)
{
    const int r = blockIdx.x;
    const int tid = threadIdx.x;
    float4 f = make_float4(0.f, 0.f, 0.f, 0.f);
    if (r < RR) {
        int t = r >> 6, n = r & 63;
        int tok = x[n * TT + t];
        f = *reinterpret_cast<const float4*>(embed_w + (size_t)tok * EE + tid * 4);
    }
    union { __nv_bfloat16 h[4]; uint2 u; } pk;
    pk.h[0] = __float2bfloat16(f.x);
    pk.h[1] = __float2bfloat16(f.y);
    pk.h[2] = __float2bfloat16(f.z);
    pk.h[3] = __float2bfloat16(f.w);
    *reinterpret_cast<uint2*>(d_Ab + (size_t)r * EE + tid * 4) = pk.u;
}

__global__ void __launch_bounds__(256) k_prepB(const float* __restrict__ trans_w)
{
    size_t idx = (size_t)blockIdx.x * blockDim.x + threadIdx.x;
    float4 f = *reinterpret_cast<const float4*>(trans_w + idx * 4);
    union { __nv_bfloat16 h[4]; uint2 u; } pk;
    pk.h[0] = __float2bfloat16(f.x);
    pk.h[1] = __float2bfloat16(f.y);
    pk.h[2] = __float2bfloat16(f.z);
    pk.h[3] = __float2bfloat16(f.w);
    *reinterpret_cast<uint2*>(d_Bb + idx * 4) = pk.u;
}

// =====================================================================
// Phase A: mma.sync bf16 GEMM, CTA tile 128x128, ktile 32, 4 stages.
// smem row layout: 32 bf16 (64B data) padded to 80B -> conflict-free LDSM.
// grid = (128 Mtiles, 128 iC), 256 threads (8 warps, 2x4).
// =====================================================================
constexpr int KTILE      = 32;
constexpr int NKT        = EE / KTILE;   // 8
constexpr int ROWB       = 80;           // bytes per smem row (5 x 16B units)
constexpr int TILE_BYTES = 128 * ROWB;   // 10240
constexpr int STAGEB     = 2 * TILE_BYTES; // A + B = 20480
constexpr int NSTAGE     = 4;
constexpr int SMEM_MMA   = NSTAGE * STAGEB; // 81920 (also >= 128*132*4 epilogue)

__device__ __forceinline__ void load_stage(uint32_t sb, int kt, int Mt, int iC, int tid)
{
#pragma unroll
    for (int it = 0; it < 4; it++) {
        int chunk = tid + it * 256;        // 0..1023
        int row   = (chunk >> 2) & 127;
        int c     = chunk & 3;
        bool isB  = chunk >= 512;
        const __nv_bfloat16* g = isB
            ? d_Bb + ((size_t)(iC * 128 + row)) * EE + kt * KTILE + c * 8
            : d_Ab + ((size_t)(Mt * 128 + row)) * EE + kt * KTILE + c * 8;
        uint32_t so = sb + (isB ? TILE_BYTES : 0) + row * ROWB + c * 16;
        cpa16(so, g);
    }
}

__global__ void __launch_bounds__(256, 2) k_mma(int dummy)
{
    extern __shared__ char smem[];
    const uint32_t sb = smem_u32(smem);
    const int Mt  = blockIdx.x;
    const int iC  = blockIdx.y;
    const int tid = threadIdx.x;
    const int wid = tid >> 5;
    const int lane = tid & 31;
    const int wm = (wid & 1) * 64;       // warp M base
    const int wn = (wid >> 1) * 32;      // warp N base

    float acc[4][4][4];
#pragma unroll
    for (int a = 0; a < 4; a++)
#pragma unroll
        for (int b = 0; b < 4; b++)
#pragma unroll
            for (int c = 0; c < 4; c++) acc[a][b][c] = 0.0f;

    // prologue: stages 0..2
#pragma unroll
    for (int s = 0; s < 3; s++) {
        load_stage(sb + s * STAGEB, s, Mt, iC, tid);
        asm volatile("cp.async.commit_group;" ::: "memory");
    }

    const int lr = lane & 15;          // ldmatrix row-within-tile
    const int lu = lane >> 4;          // ldmatrix k-unit selector

    for (int kt = 0; kt < NKT; kt++) {
        asm volatile("cp.async.wait_group %0;" :: "n"(2) : "memory");
        __syncthreads();
        if (kt + 3 < NKT) load_stage(sb + ((kt + 3) & 3) * STAGEB, kt + 3, Mt, iC, tid);
        asm volatile("cp.async.commit_group;" ::: "memory");

        uint32_t Abase = sb + (kt & 3) * STAGEB;
        uint32_t Bbase = Abase + TILE_BYTES;
#pragma unroll
        for (int s = 0; s < 2; s++) {
            uint32_t af[4][4];
#pragma unroll
            for (int mi = 0; mi < 4; mi++)
                ldsm_x4(af[mi][0], af[mi][1], af[mi][2], af[mi][3],
                        Abase + (wm + mi * 16 + lr) * ROWB + (2 * s + lu) * 16);
            uint32_t bf[2][4];
#pragma unroll
            for (int p = 0; p < 2; p++)
                ldsm_x4(bf[p][0], bf[p][1], bf[p][2], bf[p][3],
                        Bbase + (wn + p * 16 + lr) * ROWB + (2 * s + lu) * 16);
#pragma unroll
            for (int mi = 0; mi < 4; mi++)
#pragma unroll
                for (int ni = 0; ni < 4; ni++) {
                    int p = ni >> 1, hi = ni & 1;
                    mma_bf16(acc[mi][ni][0], acc[mi][ni][1], acc[mi][ni][2], acc[mi][ni][3],
                             af[mi][0], af[mi][1], af[mi][2], af[mi][3],
                             bf[p][hi], bf[p][2 + hi]);
                }
        }
    }

    // epilogue: accs -> smem (reuse operand buffers), softmax rows, fp16 store
    __syncthreads();
    float* ep = reinterpret_cast<float*>(smem);   // [128][132]
    const int er = lane >> 2;
    const int ec = (lane & 3) * 2;
#pragma unroll
    for (int mi = 0; mi < 4; mi++)
#pragma unroll
        for (int ni = 0; ni < 4; ni++) {
            int row = wm + mi * 16 + er;
            int col = wn + ni * 8 + ec;
            *reinterpret_cast<float2*>(ep + (size_t)row * 132 + col) =
                make_float2(acc[mi][ni][0], acc[mi][ni][1]);
            *reinterpret_cast<float2*>(ep + (size_t)(row + 8) * 132 + col) =
                make_float2(acc[mi][ni][2], acc[mi][ni][3]);
        }
    __syncthreads();

    {
        const int row  = tid >> 1;
        const int half = tid & 1;
        const int r    = Mt * 128 + row;
        float v[64];
        const float* rp = ep + (size_t)row * 132 + half * 64;
#pragma unroll
        for (int q = 0; q < 16; q++) {
            float4 f4 = *reinterpret_cast<const float4*>(rp + q * 4);
            v[q * 4 + 0] = f4.x; v[q * 4 + 1] = f4.y; v[q * 4 + 2] = f4.z; v[q * 4 + 3] = f4.w;
        }
        float m = -3.4e38f;
#pragma unroll
        for (int q = 0; q < 64; q++) m = fmaxf(m, v[q]);
        m = fmaxf(m, __shfl_xor_sync(0xffffffffu, m, 1));
        float s = 0.0f;
#pragma unroll
        for (int q = 0; q < 64; q++) { v[q] = exp2f((v[q] - m) * LOG2E_F); s += v[q]; }
        s += __shfl_xor_sync(0xffffffffu, s, 1);
        float inv = 1.0f / s;
        if (r < RR) {
            uint4* op = reinterpret_cast<uint4*>(
                d_P + ((size_t)r * KC + iC) * KC + half * 64);
#pragma unroll
            for (int q = 0; q < 8; q++) {
                uint4 o;
                __half2 h0 = __floats2half2_rn(v[8*q+0] * inv, v[8*q+1] * inv);
                __half2 h1 = __floats2half2_rn(v[8*q+2] * inv, v[8*q+3] * inv);
                __half2 h2 = __floats2half2_rn(v[8*q+4] * inv, v[8*q+5] * inv);
                __half2 h3 = __floats2half2_rn(v[8*q+6] * inv, v[8*q+7] * inv);
                o.x = *reinterpret_cast<uint32_t*>(&h0);
                o.y = *reinterpret_cast<uint32_t*>(&h1);
                o.z = *reinterpret_cast<uint32_t*>(&h2);
                o.w = *reinterpret_cast<uint32_t*>(&h3);
                op[q] = o;
            }
        }
    }
    (void)dummy;
}

// =====================================================================
// Emission logits GEMM + lse + gather (unchanged)
// =====================================================================
__global__ void __launch_bounds__(256) k_emit_gemm(const float* __restrict__ emit_w,
                                                   const float* __restrict__ emb_cluster_w)
{
    const int vt = blockIdx.x;
    __shared__ float avs[16][65];
    __shared__ float bvs[16][129];
    __shared__ float pmS[8][128];
    __shared__ float psS[8][128];

    const int tid   = threadIdx.x;
    const int lane  = tid & 31;
    const int wg    = tid >> 5;
    const int rbase = wg * 8;
    const int cbase = lane * 4;

    float acc[8][4];
#pragma unroll
    for (int a = 0; a < 8; a++)
#pragma unroll
        for (int b = 0; b < 4; b++) acc[a][b] = 0.0f;

    for (int k0 = 0; k0 < KC; k0 += 16) {
#pragma unroll
        for (int it = 0; it < 4; it++) {
            int u = tid + it * 256;
            int kk = u & 15, row = u >> 4;
            avs[kk][row] = emit_w[(size_t)(vt * 64 + row) * KC + k0 + kk];
        }
#pragma unroll
        for (int it = 0; it < 8; it++) {
            int u = tid + it * 256;
            int kk = u & 15, c = u >> 4;
            bvs[kk][c] = emb_cluster_w[(size_t)c * KC + k0 + kk];
        }
        __syncthreads();
#pragma unroll
        for (int kk = 0; kk < 16; kk++) {
            float av[8], bv[4];
#pragma unroll
            for (int r2 = 0; r2 < 8; r2++) av[r2] = avs[kk][rbase + r2];
#pragma unroll
            for (int c2 = 0; c2 < 4; c2++) bv[c2] = bvs[kk][cbase + c2];
#pragma unroll
            for (int r2 = 0; r2 < 8; r2++)
#pragma unroll
                for (int c2 = 0; c2 < 4; c2++)
                    acc[r2][c2] = fmaf(av[r2], bv[c2], acc[r2][c2]);
        }
        __syncthreads();
    }

    float pm[4], ps[4];
#pragma unroll
    for (int c2 = 0; c2 < 4; c2++) { pm[c2] = -3.4e38f; ps[c2] = 0.0f; }
#pragma unroll
    for (int r2 = 0; r2 < 8; r2++) {
        int v = vt * 64 + rbase + r2;
        float4 f4 = make_float4(acc[r2][0], acc[r2][1], acc[r2][2], acc[r2][3]);
        *reinterpret_cast<float4*>(&d_LogitsT[(size_t)v * KC + cbase]) = f4;
#pragma unroll
        for (int c2 = 0; c2 < 4; c2++) pm[c2] = fmaxf(pm[c2], acc[r2][c2]);
    }
#pragma unroll
    for (int r2 = 0; r2 < 8; r2++)
#pragma unroll
        for (int c2 = 0; c2 < 4; c2++)
            ps[c2] += exp2f((acc[r2][c2] - pm[c2]) * LOG2E_F);

#pragma unroll
    for (int c2 = 0; c2 < 4; c2++) { pmS[wg][cbase + c2] = pm[c2]; psS[wg][cbase + c2] = ps[c2]; }
    __syncthreads();
    if (tid < 128) {
        float m = pmS[0][tid];
#pragma unroll
        for (int w = 1; w < 8; w++) m = fmaxf(m, pmS[w][tid]);
        float s = 0.0f;
#pragma unroll
        for (int w = 0; w < 8; w++) s += psS[w][tid] * exp2f((pmS[w][tid] - m) * LOG2E_F);
        d_PM[vt * KC + tid] = m;
        d_PS[vt * KC + tid] = s;
    }
}

__global__ void k_lse_final()
{
    int c = threadIdx.x;
    float m = -3.4e38f, s = 0.0f;
    for (int b = 0; b < VTILES; b++) {
        float bm = d_PM[b * KC + c], bs = d_PS[b * KC + c];
        if (bm > m) { s = s * exp2f((m - bm) * LOG2E_F) + bs; m = bm; }
        else        { s += bs * exp2f((bm - m) * LOG2E_F); }
    }
    d_RowLse[c] = m + log2f(s) * LN2_F;
}

__global__ void __launch_bounds__(128) k_emit_add(const int* __restrict__ x)
{
    int r = blockIdx.x, j = threadIdx.x;
    int t = r >> 6, n = r & 63;
    int w = x[n * TT + t + 1];
    d_EmitAdd[(size_t)r * KC + j] = d_LogitsT[(size_t)w * KC + j] - d_RowLse[j];
}

// =====================================================================
// Phase B: sequential scan with hoisted loads
// =====================================================================
__global__ void __launch_bounds__(128) k_scan(const float* __restrict__ start_w,
                                              const float* __restrict__ start_b)
{
    const int n    = blockIdx.x;
    const int tid  = threadIdx.x;
    const int lane = tid & 31;
    const int wid  = tid >> 5;
    const int jg   = lane;
    const int ic   = wid;
    __shared__ float w_s[128];
    __shared__ float red[4][132];
    __shared__ float smax[4], ssum[4];

    float a0 = start_w[tid] + start_b[tid];
    float m = warpMax(a0);
    if (lane == 0) smax[wid] = m;
    __syncthreads();
    m = fmaxf(fmaxf(smax[0], smax[1]), fmaxf(smax[2], smax[3]));
    float e = exp2f((a0 - m) * LOG2E_F);
    float s = warpSum(e);
    if (lane == 0) ssum[wid] = s;
    __syncthreads();
    s = ssum[0] + ssum[1] + ssum[2] + ssum[3];
    float alpha = a0 - m - log2f(s) * LN2_F;
    __syncthreads();

    for (int t = 0; t < TT - 1; t++) {
        const int r = t * NB + n;

        uint2 u[32];
        const __half* Pp = d_P + (((size_t)r * KC) + ic * 32) * KC + jg * 4;
#pragma unroll
        for (int ii = 0; ii < 32; ii++)
            u[ii] = *reinterpret_cast<const uint2*>(Pp + (size_t)ii * KC);
        float ea = d_EmitAdd[(size_t)r * KC + tid];

        float mm = warpMax(alpha);
        if (lane == 0) smax[wid] = mm;
        __syncthreads();
        mm = fmaxf(fmaxf(smax[0], smax[1]), fmaxf(smax[2], smax[3]));
        w_s[tid] = exp2f((alpha - mm) * LOG2E_F);
        __syncthreads();

        float acc0 = 0.f, acc1 = 0.f, acc2 = 0.f, acc3 = 0.f;
#pragma unroll
        for (int ii = 0; ii < 32; ii++) {
            float wi = w_s[ic * 32 + ii];
            __half2 h01 = *reinterpret_cast<__half2*>(&u[ii].x);
            __half2 h23 = *reinterpret_cast<__half2*>(&u[ii].y);
            float2 f01 = __half22float2(h01);
            float2 f23 = __half22float2(h23);
            acc0 = fmaf(wi, f01.x, acc0);
            acc1 = fmaf(wi, f01.y, acc1);
            acc2 = fmaf(wi, f23.x, acc2);
            acc3 = fmaf(wi, f23.y, acc3);
        }
        red[ic][jg * 4 + 0] = acc0;
        red[ic][jg * 4 + 1] = acc1;
        red[ic][jg * 4 + 2] = acc2;
        red[ic][jg * 4 + 3] = acc3;
        __syncthreads();
        float tot = red[0][tid] + red[1][tid] + red[2][tid] + red[3][tid];
        alpha = mm + log2f(tot) * LN2_F + ea;
        __syncthreads();
    }

    float mm = warpMax(alpha);
    if (lane == 0) smax[wid] = mm;
    __syncthreads();
    mm = fmaxf(fmaxf(smax[0], smax[1]), fmaxf(smax[2], smax[3]));
    float ee = exp2f((alpha - mm) * LOG2E_F);
    float ss = warpSum(ee);
    if (lane == 0) ssum[wid] = ss;
    __syncthreads();
    if (tid == 0) {
        float stot = ssum[0] + ssum[1] + ssum[2] + ssum[3];
        d_Chain[n] = mm + log2f(stot) * LN2_F;
    }
}

__global__ void k_final(float* out, int out_size)
{
    __shared__ float sh;
    if (threadIdx.x == 0) {
        float s = 0.0f;
        for (int i = 0; i < NB; i++) s += d_Chain[i];
        sh = -s / (float)NB;
    }
    __syncthreads();
    for (int i = threadIdx.x; i < out_size; i += blockDim.x) out[i] = sh;
}

extern "C" void kernel_launch(void* const* d_in, const int* in_sizes, int n_in,
                              void* d_out, int out_size)
{
    (void)in_sizes; (void)n_in;
    const int*   x             = (const int*)d_in[0];
    const float* embed_w       = (const float*)d_in[1];
    const float* trans_w       = (const float*)d_in[2];
    const float* start_w       = (const float*)d_in[3];
    const float* start_b       = (const float*)d_in[4];
    const float* emb_cluster_w = (const float*)d_in[5];
    const float* emit_w        = (const float*)d_in[6];

    cudaFuncSetAttribute(k_mma, cudaFuncAttributeMaxDynamicSharedMemorySize, SMEM_MMA);

    k_prepB<<<4096, 256>>>(trans_w);
    k_prepA<<<RPAD, 64>>>(x, embed_w);
    k_emit_gemm<<<VTILES, 256>>>(emit_w, emb_cluster_w);
    k_lse_final<<<1, 128>>>();
    k_emit_add<<<RR, 128>>>(x);
    k_mma<<<dim3(128, 128), 256, SMEM_MMA>>>(0);
    k_scan<<<NB, 128>>>(start_w, start_b);
    k_final<<<1, 64>>>((float*)d_out, out_size);
}

// round 4
// speedup vs baseline: 5.9977x; 1.1443x over previous
#include <cuda_runtime.h>
#include <cuda_fp16.h>
#include <cuda_bf16.h>
#include <cstdint>

#define LOG2E_F 1.4426950408889634f
#define LN2_F   0.6931471805599453f

constexpr int NB = 64;       // batch N
constexpr int TT = 256;      // T
constexpr int VV = 32000;    // vocab
constexpr int EE = 256;      // embed dim
constexpr int KC = 128;      // clusters K
constexpr int RR = (TT - 1) * NB;   // 16320 (t,n) rows
constexpr int RPAD = 16384;         // padded rows for MMA tiling
constexpr int VTILES = VV / 64;     // 500

// ------- static scratch (allocation-free rule: __device__ globals) -------
__device__ __align__(16) __half d_P[(size_t)RR * KC * KC];   // [r][i][j] transition probs (fp16)
__device__ __align__(16) float  d_EmitAdd[(size_t)RR * KC];  // [r][j]
__device__ __align__(16) float  d_LogitsT[(size_t)VV * KC];  // [v][c]
__device__ __align__(16) __nv_bfloat16 d_Ab[(size_t)RPAD * EE]; // gathered embeddings bf16
__device__ __align__(16) __nv_bfloat16 d_Bb[(size_t)KC * KC * EE]; // trans_w bf16
__device__ float  d_PM[VTILES * KC];
__device__ float  d_PS[VTILES * KC];
__device__ float  d_RowLse[KC];
__device__ float  d_Chain[NB];

__device__ __forceinline__ uint32_t smem_u32(const void* p) {
    uint32_t a;
    asm("{ .reg .u64 t; cvta.to.shared.u64 t, %1; cvt.u32.u64 %0, t; }" : "=r"(a) : "l"(p));
    return a;
}
__device__ __forceinline__ void cpa16(uint32_t saddr, const void* g) {
    asm volatile("cp.async.cg.shared.global [%0], [%1], 16;" :: "r"(saddr), "l"(g));
}
__device__ __forceinline__ void cpa4(uint32_t saddr, const void* g) {
    asm volatile("cp.async.ca.shared.global [%0], [%1], 4;" :: "r"(saddr), "l"(g));
}
__device__ __forceinline__ void ldsm_x4(uint32_t& r0, uint32_t& r1, uint32_t& r2, uint32_t& r3,
                                        uint32_t addr) {
    asm volatile("ldmatrix.sync.aligned.m8n8.x4.shared.b16 {%0,%1,%2,%3}, [%4];"
                 : "=r"(r0), "=r"(r1), "=r"(r2), "=r"(r3) : "r"(addr));
}
__device__ __forceinline__ void mma_bf16(float& d0, float& d1, float& d2, float& d3,
                                         uint32_t a0, uint32_t a1, uint32_t a2, uint32_t a3,
                                         uint32_t b0, uint32_t b1) {
    asm volatile("mma.sync.aligned.m16n8k16.row.col.f32.bf16.bf16.f32 "
                 "{%0,%1,%2,%3}, {%4,%5,%6,%7}, {%8,%9}, {%0,%1,%2,%3};"
                 : "+f"(d0), "+f"(d1), "+f"(d2), "+f"(d3)
                 : "r"(a0), "r"(a1), "r"(a2), "r"(a3), "r"(b0), "r"(b1));
}

__device__ __forceinline__ float warpMax(float v) {
#pragma unroll
    for (int o = 16; o; o >>= 1) v = fmaxf(v, __shfl_xor_sync(0xffffffffu, v, o));
    return v;
}
__device__ __forceinline__ float warpSum(float v) {
#pragma unroll
    for (int o = 16; o; o >>= 1) v += __shfl_xor_sync(0xffffffffu, v, o);
    return v;
}

// =====================================================================
// Operand prep
// =====================================================================
__global__ void __launch_bounds__(64) k_prepA(const int* __restrict__ x,
                                              const float* __restrict__ embed_w)
{
    const int r = blockIdx.x;
    const int tid = threadIdx.x;
    float4 f = make_float4(0.f, 0.f, 0.f, 0.f);
    if (r < RR) {
        int t = r >> 6, n = r & 63;
        int tok = x[n * TT + t];
        f = *reinterpret_cast<const float4*>(embed_w + (size_t)tok * EE + tid * 4);
    }
    union { __nv_bfloat16 h[4]; uint2 u; } pk;
    pk.h[0] = __float2bfloat16(f.x);
    pk.h[1] = __float2bfloat16(f.y);
    pk.h[2] = __float2bfloat16(f.z);
    pk.h[3] = __float2bfloat16(f.w);
    *reinterpret_cast<uint2*>(d_Ab + (size_t)r * EE + tid * 4) = pk.u;
}

__global__ void __launch_bounds__(256) k_prepB(const float* __restrict__ trans_w)
{
    size_t idx = (size_t)blockIdx.x * blockDim.x + threadIdx.x;
    float4 f = *reinterpret_cast<const float4*>(trans_w + idx * 4);
    union { __nv_bfloat16 h[4]; uint2 u; } pk;
    pk.h[0] = __float2bfloat16(f.x);
    pk.h[1] = __float2bfloat16(f.y);
    pk.h[2] = __float2bfloat16(f.z);
    pk.h[3] = __float2bfloat16(f.w);
    *reinterpret_cast<uint2*>(d_Bb + idx * 4) = pk.u;
}

// =====================================================================
// Phase A: mma.sync bf16 GEMM, CTA tile 128x128, ktile 32, 4 stages.
// =====================================================================
constexpr int KTILE      = 32;
constexpr int NKT        = EE / KTILE;   // 8
constexpr int ROWB       = 80;           // bytes per smem row
constexpr int TILE_BYTES = 128 * ROWB;   // 10240
constexpr int STAGEB     = 2 * TILE_BYTES; // 20480
constexpr int NSTAGE     = 4;
constexpr int SMEM_MMA   = NSTAGE * STAGEB; // 81920

__device__ __forceinline__ void load_stage(uint32_t sb, int kt, int Mt, int iC, int tid)
{
#pragma unroll
    for (int it = 0; it < 4; it++) {
        int chunk = tid + it * 256;
        int row   = (chunk >> 2) & 127;
        int c     = chunk & 3;
        bool isB  = chunk >= 512;
        const __nv_bfloat16* g = isB
            ? d_Bb + ((size_t)(iC * 128 + row)) * EE + kt * KTILE + c * 8
            : d_Ab + ((size_t)(Mt * 128 + row)) * EE + kt * KTILE + c * 8;
        uint32_t so = sb + (isB ? TILE_BYTES : 0) + row * ROWB + c * 16;
        cpa16(so, g);
    }
}

__global__ void __launch_bounds__(256, 2) k_mma(int dummy)
{
    extern __shared__ char smem[];
    const uint32_t sb = smem_u32(smem);
    const int Mt  = blockIdx.x;
    const int iC  = blockIdx.y;
    const int tid = threadIdx.x;
    const int wid = tid >> 5;
    const int lane = tid & 31;
    const int wm = (wid & 1) * 64;
    const int wn = (wid >> 1) * 32;

    float acc[4][4][4];
#pragma unroll
    for (int a = 0; a < 4; a++)
#pragma unroll
        for (int b = 0; b < 4; b++)
#pragma unroll
            for (int c = 0; c < 4; c++) acc[a][b][c] = 0.0f;

#pragma unroll
    for (int s = 0; s < 3; s++) {
        load_stage(sb + s * STAGEB, s, Mt, iC, tid);
        asm volatile("cp.async.commit_group;" ::: "memory");
    }

    const int lr = lane & 15;
    const int lu = lane >> 4;

    for (int kt = 0; kt < NKT; kt++) {
        asm volatile("cp.async.wait_group %0;" :: "n"(2) : "memory");
        __syncthreads();
        if (kt + 3 < NKT) load_stage(sb + ((kt + 3) & 3) * STAGEB, kt + 3, Mt, iC, tid);
        asm volatile("cp.async.commit_group;" ::: "memory");

        uint32_t Abase = sb + (kt & 3) * STAGEB;
        uint32_t Bbase = Abase + TILE_BYTES;
#pragma unroll
        for (int s = 0; s < 2; s++) {
            uint32_t af[4][4];
#pragma unroll
            for (int mi = 0; mi < 4; mi++)
                ldsm_x4(af[mi][0], af[mi][1], af[mi][2], af[mi][3],
                        Abase + (wm + mi * 16 + lr) * ROWB + (2 * s + lu) * 16);
            uint32_t bf[2][4];
#pragma unroll
            for (int p = 0; p < 2; p++)
                ldsm_x4(bf[p][0], bf[p][1], bf[p][2], bf[p][3],
                        Bbase + (wn + p * 16 + lr) * ROWB + (2 * s + lu) * 16);
#pragma unroll
            for (int mi = 0; mi < 4; mi++)
#pragma unroll
                for (int ni = 0; ni < 4; ni++) {
                    int p = ni >> 1, hi = ni & 1;
                    mma_bf16(acc[mi][ni][0], acc[mi][ni][1], acc[mi][ni][2], acc[mi][ni][3],
                             af[mi][0], af[mi][1], af[mi][2], af[mi][3],
                             bf[p][hi], bf[p][2 + hi]);
                }
        }
    }

    __syncthreads();
    float* ep = reinterpret_cast<float*>(smem);   // [128][132]
    const int er = lane >> 2;
    const int ec = (lane & 3) * 2;
#pragma unroll
    for (int mi = 0; mi < 4; mi++)
#pragma unroll
        for (int ni = 0; ni < 4; ni++) {
            int row = wm + mi * 16 + er;
            int col = wn + ni * 8 + ec;
            *reinterpret_cast<float2*>(ep + (size_t)row * 132 + col) =
                make_float2(acc[mi][ni][0], acc[mi][ni][1]);
            *reinterpret_cast<float2*>(ep + (size_t)(row + 8) * 132 + col) =
                make_float2(acc[mi][ni][2], acc[mi][ni][3]);
        }
    __syncthreads();

    {
        const int row  = tid >> 1;
        const int half = tid & 1;
        const int r    = Mt * 128 + row;
        float v[64];
        const float* rp = ep + (size_t)row * 132 + half * 64;
#pragma unroll
        for (int q = 0; q < 16; q++) {
            float4 f4 = *reinterpret_cast<const float4*>(rp + q * 4);
            v[q * 4 + 0] = f4.x; v[q * 4 + 1] = f4.y; v[q * 4 + 2] = f4.z; v[q * 4 + 3] = f4.w;
        }
        float m = -3.4e38f;
#pragma unroll
        for (int q = 0; q < 64; q++) m = fmaxf(m, v[q]);
        m = fmaxf(m, __shfl_xor_sync(0xffffffffu, m, 1));
        float s = 0.0f;
#pragma unroll
        for (int q = 0; q < 64; q++) { v[q] = exp2f((v[q] - m) * LOG2E_F); s += v[q]; }
        s += __shfl_xor_sync(0xffffffffu, s, 1);
        float inv = 1.0f / s;
        if (r < RR) {
            uint4* op = reinterpret_cast<uint4*>(
                d_P + ((size_t)r * KC + iC) * KC + half * 64);
#pragma unroll
            for (int q = 0; q < 8; q++) {
                uint4 o;
                __half2 h0 = __floats2half2_rn(v[8*q+0] * inv, v[8*q+1] * inv);
                __half2 h1 = __floats2half2_rn(v[8*q+2] * inv, v[8*q+3] * inv);
                __half2 h2 = __floats2half2_rn(v[8*q+4] * inv, v[8*q+5] * inv);
                __half2 h3 = __floats2half2_rn(v[8*q+6] * inv, v[8*q+7] * inv);
                o.x = *reinterpret_cast<uint32_t*>(&h0);
                o.y = *reinterpret_cast<uint32_t*>(&h1);
                o.z = *reinterpret_cast<uint32_t*>(&h2);
                o.w = *reinterpret_cast<uint32_t*>(&h3);
                op[q] = o;
            }
        }
    }
    (void)dummy;
}

// =====================================================================
// Emission logits GEMM + parallel lse + gather
// =====================================================================
__global__ void __launch_bounds__(256) k_emit_gemm(const float* __restrict__ emit_w,
                                                   const float* __restrict__ emb_cluster_w)
{
    const int vt = blockIdx.x;
    __shared__ float avs[16][65];
    __shared__ float bvs[16][129];
    __shared__ float pmS[8][128];
    __shared__ float psS[8][128];

    const int tid   = threadIdx.x;
    const int lane  = tid & 31;
    const int wg    = tid >> 5;
    const int rbase = wg * 8;
    const int cbase = lane * 4;

    float acc[8][4];
#pragma unroll
    for (int a = 0; a < 8; a++)
#pragma unroll
        for (int b = 0; b < 4; b++) acc[a][b] = 0.0f;

    for (int k0 = 0; k0 < KC; k0 += 16) {
#pragma unroll
        for (int it = 0; it < 4; it++) {
            int u = tid + it * 256;
            int kk = u & 15, row = u >> 4;
            avs[kk][row] = emit_w[(size_t)(vt * 64 + row) * KC + k0 + kk];
        }
#pragma unroll
        for (int it = 0; it < 8; it++) {
            int u = tid + it * 256;
            int kk = u & 15, c = u >> 4;
            bvs[kk][c] = emb_cluster_w[(size_t)c * KC + k0 + kk];
        }
        __syncthreads();
#pragma unroll
        for (int kk = 0; kk < 16; kk++) {
            float av[8], bv[4];
#pragma unroll
            for (int r2 = 0; r2 < 8; r2++) av[r2] = avs[kk][rbase + r2];
#pragma unroll
            for (int c2 = 0; c2 < 4; c2++) bv[c2] = bvs[kk][cbase + c2];
#pragma unroll
            for (int r2 = 0; r2 < 8; r2++)
#pragma unroll
                for (int c2 = 0; c2 < 4; c2++)
                    acc[r2][c2] = fmaf(av[r2], bv[c2], acc[r2][c2]);
        }
        __syncthreads();
    }

    float pm[4], ps[4];
#pragma unroll
    for (int c2 = 0; c2 < 4; c2++) { pm[c2] = -3.4e38f; ps[c2] = 0.0f; }
#pragma unroll
    for (int r2 = 0; r2 < 8; r2++) {
        int v = vt * 64 + rbase + r2;
        float4 f4 = make_float4(acc[r2][0], acc[r2][1], acc[r2][2], acc[r2][3]);
        *reinterpret_cast<float4*>(&d_LogitsT[(size_t)v * KC + cbase]) = f4;
#pragma unroll
        for (int c2 = 0; c2 < 4; c2++) pm[c2] = fmaxf(pm[c2], acc[r2][c2]);
    }
#pragma unroll
    for (int r2 = 0; r2 < 8; r2++)
#pragma unroll
        for (int c2 = 0; c2 < 4; c2++)
            ps[c2] += exp2f((acc[r2][c2] - pm[c2]) * LOG2E_F);

#pragma unroll
    for (int c2 = 0; c2 < 4; c2++) { pmS[wg][cbase + c2] = pm[c2]; psS[wg][cbase + c2] = ps[c2]; }
    __syncthreads();
    if (tid < 128) {
        float m = pmS[0][tid];
#pragma unroll
        for (int w = 1; w < 8; w++) m = fmaxf(m, pmS[w][tid]);
        float s = 0.0f;
#pragma unroll
        for (int w = 0; w < 8; w++) s += psS[w][tid] * exp2f((pmS[w][tid] - m) * LOG2E_F);
        d_PM[vt * KC + tid] = m;
        d_PS[vt * KC + tid] = s;
    }
}

// 1024 threads: 8 partial lanes per cluster; two independent-load passes
__global__ void __launch_bounds__(1024) k_lse_final()
{
    __shared__ float sm[8][128];
    __shared__ float sp[8][128];
    const int c    = threadIdx.x & 127;
    const int part = threadIdx.x >> 7;   // 0..7

    float m = -3.4e38f;
    for (int b = part; b < VTILES; b += 8)
        m = fmaxf(m, d_PM[b * KC + c]);
    sm[part][c] = m;
    __syncthreads();
    float gm = sm[0][c];
#pragma unroll
    for (int w = 1; w < 8; w++) gm = fmaxf(gm, sm[w][c]);

    float s = 0.0f;
    for (int b = part; b < VTILES; b += 8)
        s += d_PS[b * KC + c] * exp2f((d_PM[b * KC + c] - gm) * LOG2E_F);
    sp[part][c] = s;
    __syncthreads();
    if (part == 0) {
        float tot = 0.0f;
#pragma unroll
        for (int w = 0; w < 8; w++) tot += sp[w][c];
        d_RowLse[c] = gm + log2f(tot) * LN2_F;
    }
}

__global__ void __launch_bounds__(128) k_emit_add(const int* __restrict__ x)
{
    int r = blockIdx.x, j = threadIdx.x;
    int t = r >> 6, n = r & 63;
    int w = x[n * TT + t + 1];
    d_EmitAdd[(size_t)r * KC + j] = d_LogitsT[(size_t)w * KC + j] - d_RowLse[j];
}

// =====================================================================
// Phase B: sequential scan, 3-stage cp.async pipeline (P + EmitAdd)
// =====================================================================
constexpr int PBUF      = KC * KC * 2;           // 32768 per stage
constexpr int EABUF     = KC * 4;                // 512 per stage
constexpr int SCAN_SMEM = 3 * (PBUF + EABUF);    // 99840

__global__ void __launch_bounds__(128) k_scan(const float* __restrict__ start_w,
                                              const float* __restrict__ start_b)
{
    extern __shared__ __align__(16) char ps[];
    __shared__ float w_s[128];
    __shared__ float red[4][132];
    __shared__ float smax[4], ssum[4];

    const int n    = blockIdx.x;
    const int tid  = threadIdx.x;
    const int lane = tid & 31;
    const int wid  = tid >> 5;
    const int jg   = lane;
    const int ic   = wid;
    const uint32_t sbase  = smem_u32(ps);
    const uint32_t eabase = sbase + 3 * PBUF;

    auto prefetch = [&](int t) {
        const int r = t * NB + n;
        const char* gp = reinterpret_cast<const char*>(d_P + (size_t)r * KC * KC);
        uint32_t dst = sbase + (t % 3) * PBUF;
#pragma unroll
        for (int k = 0; k < 16; k++) {
            int idx = tid + k * 128;
            cpa16(dst + idx * 16, gp + idx * 16);
        }
        cpa4(eabase + (t % 3) * EABUF + tid * 4,
             d_EmitAdd + (size_t)r * KC + tid);
    };

    prefetch(0);
    asm volatile("cp.async.commit_group;" ::: "memory");
    prefetch(1);
    asm volatile("cp.async.commit_group;" ::: "memory");

    // pre = log_softmax(start_w[:,0] + start_b)
    float a0 = start_w[tid] + start_b[tid];
    float m = warpMax(a0);
    if (lane == 0) smax[wid] = m;
    __syncthreads();
    m = fmaxf(fmaxf(smax[0], smax[1]), fmaxf(smax[2], smax[3]));
    float e = exp2f((a0 - m) * LOG2E_F);
    float s = warpSum(e);
    if (lane == 0) ssum[wid] = s;
    __syncthreads();
    s = ssum[0] + ssum[1] + ssum[2] + ssum[3];
    float alpha = a0 - m - log2f(s) * LN2_F;
    __syncthreads();

    for (int t = 0; t < TT - 1; t++) {
        if (t + 2 < TT - 1) prefetch(t + 2);
        asm volatile("cp.async.commit_group;" ::: "memory");

        float mm = warpMax(alpha);
        if (lane == 0) smax[wid] = mm;
        __syncthreads();
        mm = fmaxf(fmaxf(smax[0], smax[1]), fmaxf(smax[2], smax[3]));
        w_s[tid] = exp2f((alpha - mm) * LOG2E_F);
        asm volatile("cp.async.wait_group %0;" :: "n"(2) : "memory");
        __syncthreads();

        const uint32_t pb = sbase + (t % 3) * PBUF;
        float acc0 = 0.f, acc1 = 0.f, acc2 = 0.f, acc3 = 0.f;
#pragma unroll
        for (int ii = 0; ii < 32; ii++) {
            const int i = ic * 32 + ii;
            uint2 u = *reinterpret_cast<const uint2*>(ps + (pb - sbase) + i * 256 + jg * 8);
            float wi = w_s[i];
            __half2 h01 = *reinterpret_cast<__half2*>(&u.x);
            __half2 h23 = *reinterpret_cast<__half2*>(&u.y);
            float2 f01 = __half22float2(h01);
            float2 f23 = __half22float2(h23);
            acc0 = fmaf(wi, f01.x, acc0);
            acc1 = fmaf(wi, f01.y, acc1);
            acc2 = fmaf(wi, f23.x, acc2);
            acc3 = fmaf(wi, f23.y, acc3);
        }
        red[ic][jg * 4 + 0] = acc0;
        red[ic][jg * 4 + 1] = acc1;
        red[ic][jg * 4 + 2] = acc2;
        red[ic][jg * 4 + 3] = acc3;
        __syncthreads();
        float tot = red[0][tid] + red[1][tid] + red[2][tid] + red[3][tid];
        float ea = *reinterpret_cast<const float*>(ps + 3 * PBUF + (t % 3) * EABUF + tid * 4);
        alpha = mm + log2f(tot) * LN2_F + ea;
        __syncthreads();
    }

    float mm = warpMax(alpha);
    if (lane == 0) smax[wid] = mm;
    __syncthreads();
    mm = fmaxf(fmaxf(smax[0], smax[1]), fmaxf(smax[2], smax[3]));
    float ee = exp2f((alpha - mm) * LOG2E_F);
    float ss = warpSum(ee);
    if (lane == 0) ssum[wid] = ss;
    __syncthreads();
    if (tid == 0) {
        float stot = ssum[0] + ssum[1] + ssum[2] + ssum[3];
        d_Chain[n] = mm + log2f(stot) * LN2_F;
    }
}

__global__ void k_final(float* out, int out_size)
{
    __shared__ float sh;
    if (threadIdx.x == 0) {
        float s = 0.0f;
        for (int i = 0; i < NB; i++) s += d_Chain[i];
        sh = -s / (float)NB;
    }
    __syncthreads();
    for (int i = threadIdx.x; i < out_size; i += blockDim.x) out[i] = sh;
}

extern "C" void kernel_launch(void* const* d_in, const int* in_sizes, int n_in,
                              void* d_out, int out_size)
{
    (void)in_sizes; (void)n_in;
    const int*   x             = (const int*)d_in[0];
    const float* embed_w       = (const float*)d_in[1];
    const float* trans_w       = (const float*)d_in[2];
    const float* start_w       = (const float*)d_in[3];
    const float* start_b       = (const float*)d_in[4];
    const float* emb_cluster_w = (const float*)d_in[5];
    const float* emit_w        = (const float*)d_in[6];

    cudaFuncSetAttribute(k_mma, cudaFuncAttributeMaxDynamicSharedMemorySize, SMEM_MMA);
    cudaFuncSetAttribute(k_scan, cudaFuncAttributeMaxDynamicSharedMemorySize, SCAN_SMEM);

    k_prepB<<<4096, 256>>>(trans_w);
    k_prepA<<<RPAD, 64>>>(x, embed_w);
    k_emit_gemm<<<VTILES, 256>>>(emit_w, emb_cluster_w);
    k_lse_final<<<1, 1024>>>();
    k_emit_add<<<RR, 128>>>(x);
    k_mma<<<dim3(128, 128), 256, SMEM_MMA>>>(0);
    k_scan<<<NB, 128, SCAN_SMEM>>>(start_w, start_b);
    k_final<<<1, 64>>>((float*)d_out, out_size);
}

// round 5
// speedup vs baseline: 6.6598x; 1.1104x over previous
#include <cuda_runtime.h>
#include <cuda_fp16.h>
#include <cuda_bf16.h>
#include <cuda_fp8.h>
#include <cstdint>

#define LOG2E_F 1.4426950408889634f
#define LN2_F   0.6931471805599453f

constexpr int NB = 64;       // batch N
constexpr int TT = 256;      // T
constexpr int VV = 32000;    // vocab
constexpr int EE = 256;      // embed dim
constexpr int KC = 128;      // clusters K
constexpr int RR = (TT - 1) * NB;   // 16320 (t,n) rows
constexpr int RPAD = 16384;         // padded unique-slot capacity
constexpr int VTILES = VV / 64;     // 500

// ------- static scratch (__device__ globals; no allocation allowed) -------
__device__ __align__(16) __nv_fp8_storage_t d_P8[(size_t)RPAD * KC * KC]; // [slot][i][j] fp8 probs
__device__ __align__(16) float  d_LogitsT[(size_t)VV * KC];  // [v][c]
__device__ __align__(16) __nv_bfloat16 d_Ab[(size_t)RPAD * EE]; // unique-token embeddings bf16
__device__ __align__(16) __nv_bfloat16 d_Bb[(size_t)KC * KC * EE]; // trans_w bf16
__device__ float  d_PM[VTILES * KC];
__device__ float  d_PS[VTILES * KC];
__device__ float  d_RowLse[KC];
__device__ float  d_Chain[NB];
__device__ int    d_Mark[VV];
__device__ int    d_Slot[VV];
__device__ int    d_Inv[RPAD];
__device__ int    d_RowSlot[RR];
__device__ int    d_Uc;

__device__ __forceinline__ uint32_t smem_u32(const void* p) {
    uint32_t a;
    asm("{ .reg .u64 t; cvta.to.shared.u64 t, %1; cvt.u32.u64 %0, t; }" : "=r"(a) : "l"(p));
    return a;
}
__device__ __forceinline__ void cpa16(uint32_t saddr, const void* g) {
    asm volatile("cp.async.cg.shared.global [%0], [%1], 16;" :: "r"(saddr), "l"(g));
}
__device__ __forceinline__ void cpa4(uint32_t saddr, const void* g) {
    asm volatile("cp.async.ca.shared.global [%0], [%1], 4;" :: "r"(saddr), "l"(g));
}
__device__ __forceinline__ void ldsm_x4(uint32_t& r0, uint32_t& r1, uint32_t& r2, uint32_t& r3,
                                        uint32_t addr) {
    asm volatile("ldmatrix.sync.aligned.m8n8.x4.shared.b16 {%0,%1,%2,%3}, [%4];"
                 : "=r"(r0), "=r"(r1), "=r"(r2), "=r"(r3) : "r"(addr));
}
__device__ __forceinline__ void mma_bf16(float& d0, float& d1, float& d2, float& d3,
                                         uint32_t a0, uint32_t a1, uint32_t a2, uint32_t a3,
                                         uint32_t b0, uint32_t b1) {
    asm volatile("mma.sync.aligned.m16n8k16.row.col.f32.bf16.bf16.f32 "
                 "{%0,%1,%2,%3}, {%4,%5,%6,%7}, {%8,%9}, {%0,%1,%2,%3};"
                 : "+f"(d0), "+f"(d1), "+f"(d2), "+f"(d3)
                 : "r"(a0), "r"(a1), "r"(a2), "r"(a3), "r"(b0), "r"(b1));
}

__device__ __forceinline__ float warpMax(float v) {
#pragma unroll
    for (int o = 16; o; o >>= 1) v = fmaxf(v, __shfl_xor_sync(0xffffffffu, v, o));
    return v;
}
__device__ __forceinline__ float warpSum(float v) {
#pragma unroll
    for (int o = 16; o; o >>= 1) v += __shfl_xor_sync(0xffffffffu, v, o);
    return v;
}

// =====================================================================
// Token dedup: zero marks -> mark -> prefix scan -> row slots
// =====================================================================
__global__ void __launch_bounds__(256) k_zero()
{
    int i = blockIdx.x * 256 + threadIdx.x;
    if (i < VV) d_Mark[i] = 0;
}

__global__ void __launch_bounds__(256) k_mark(const int* __restrict__ x)
{
    int r = blockIdx.x * 256 + threadIdx.x;
    if (r < RR) {
        int t = r >> 6, n = r & 63;
        d_Mark[x[n * TT + t]] = 1;
    }
}

__global__ void __launch_bounds__(1024) k_slot()
{
    __shared__ int wsum[32];
    __shared__ int sbase;
    const int tid = threadIdx.x, lane = tid & 31, wid = tid >> 5;
    if (tid == 0) sbase = 0;
    __syncthreads();

    for (int c = 0; c < 32; c++) {
        int v = c * 1024 + tid;
        int mv = (v < VV) ? d_Mark[v] : 0;
        int sc = mv;
#pragma unroll
        for (int o = 1; o < 32; o <<= 1) {
            int t2 = __shfl_up_sync(0xffffffffu, sc, o);
            if (lane >= o) sc += t2;
        }
        if (lane == 31) wsum[wid] = sc;
        __syncthreads();
        if (wid == 0) {
            int wv = wsum[lane];
#pragma unroll
            for (int o = 1; o < 32; o <<= 1) {
                int t2 = __shfl_up_sync(0xffffffffu, wv, o);
                if (lane >= o) wv += t2;
            }
            wsum[lane] = wv;
        }
        __syncthreads();
        int excl = sc - mv + (wid ? wsum[wid - 1] : 0);
        if (mv) {
            int slot = sbase + excl;
            d_Slot[v] = slot;
            d_Inv[slot] = v;
        }
        __syncthreads();
        if (tid == 0) sbase += wsum[31];
        __syncthreads();
    }
    if (tid == 0) d_Uc = sbase;
}

__global__ void __launch_bounds__(256) k_rowslot(const int* __restrict__ x)
{
    int r = blockIdx.x * 256 + threadIdx.x;
    if (r < RR) {
        int t = r >> 6, n = r & 63;
        d_RowSlot[r] = d_Slot[x[n * TT + t]];
    }
}

// =====================================================================
// Operand prep (unique tokens only)
// =====================================================================
__global__ void __launch_bounds__(64) k_prepA(const float* __restrict__ embed_w)
{
    const int u = blockIdx.x;
    if (u >= d_Uc) return;
    const int tid = threadIdx.x;
    int tok = d_Inv[u];
    float4 f = *reinterpret_cast<const float4*>(embed_w + (size_t)tok * EE + tid * 4);
    union { __nv_bfloat16 h[4]; uint2 q; } pk;
    pk.h[0] = __float2bfloat16(f.x);
    pk.h[1] = __float2bfloat16(f.y);
    pk.h[2] = __float2bfloat16(f.z);
    pk.h[3] = __float2bfloat16(f.w);
    *reinterpret_cast<uint2*>(d_Ab + (size_t)u * EE + tid * 4) = pk.q;
}

__global__ void __launch_bounds__(256) k_prepB(const float* __restrict__ trans_w)
{
    size_t idx = (size_t)blockIdx.x * blockDim.x + threadIdx.x;
    float4 f = *reinterpret_cast<const float4*>(trans_w + idx * 4);
    union { __nv_bfloat16 h[4]; uint2 q; } pk;
    pk.h[0] = __float2bfloat16(f.x);
    pk.h[1] = __float2bfloat16(f.y);
    pk.h[2] = __float2bfloat16(f.z);
    pk.h[3] = __float2bfloat16(f.w);
    *reinterpret_cast<uint2*>(d_Bb + idx * 4) = pk.q;
}

// =====================================================================
// Phase A: mma.sync bf16 GEMM over unique rows; fp8 softmax epilogue.
// =====================================================================
constexpr int NKT        = EE / 32;      // 8
constexpr int ROWB       = 80;
constexpr int TILE_BYTES = 128 * ROWB;   // 10240
constexpr int STAGEB     = 2 * TILE_BYTES;
constexpr int SMEM_MMA   = 4 * STAGEB;   // 81920

__device__ __forceinline__ void load_stage(uint32_t sb, int kt, int Mt, int iC, int tid)
{
#pragma unroll
    for (int it = 0; it < 4; it++) {
        int chunk = tid + it * 256;
        int row   = (chunk >> 2) & 127;
        int c     = chunk & 3;
        bool isB  = chunk >= 512;
        const __nv_bfloat16* g = isB
            ? d_Bb + ((size_t)(iC * 128 + row)) * EE + kt * 32 + c * 8
            : d_Ab + ((size_t)(Mt * 128 + row)) * EE + kt * 32 + c * 8;
        uint32_t so = sb + (isB ? TILE_BYTES : 0) + row * ROWB + c * 16;
        cpa16(so, g);
    }
}

__global__ void __launch_bounds__(256, 2) k_mma(int dummy)
{
    const int U = d_Uc;
    const int Mt  = blockIdx.x;
    if (Mt * 128 >= U) return;
    extern __shared__ char smem[];
    const uint32_t sb = smem_u32(smem);
    const int iC  = blockIdx.y;
    const int tid = threadIdx.x;
    const int wid = tid >> 5;
    const int lane = tid & 31;
    const int wm = (wid & 1) * 64;
    const int wn = (wid >> 1) * 32;

    float acc[4][4][4];
#pragma unroll
    for (int a = 0; a < 4; a++)
#pragma unroll
        for (int b = 0; b < 4; b++)
#pragma unroll
            for (int c = 0; c < 4; c++) acc[a][b][c] = 0.0f;

#pragma unroll
    for (int s = 0; s < 3; s++) {
        load_stage(sb + s * STAGEB, s, Mt, iC, tid);
        asm volatile("cp.async.commit_group;" ::: "memory");
    }

    const int lr = lane & 15;
    const int lu = lane >> 4;

    for (int kt = 0; kt < NKT; kt++) {
        asm volatile("cp.async.wait_group %0;" :: "n"(2) : "memory");
        __syncthreads();
        if (kt + 3 < NKT) load_stage(sb + ((kt + 3) & 3) * STAGEB, kt + 3, Mt, iC, tid);
        asm volatile("cp.async.commit_group;" ::: "memory");

        uint32_t Abase = sb + (kt & 3) * STAGEB;
        uint32_t Bbase = Abase + TILE_BYTES;
#pragma unroll
        for (int s = 0; s < 2; s++) {
            uint32_t af[4][4];
#pragma unroll
            for (int mi = 0; mi < 4; mi++)
                ldsm_x4(af[mi][0], af[mi][1], af[mi][2], af[mi][3],
                        Abase + (wm + mi * 16 + lr) * ROWB + (2 * s + lu) * 16);
            uint32_t bf[2][4];
#pragma unroll
            for (int p = 0; p < 2; p++)
                ldsm_x4(bf[p][0], bf[p][1], bf[p][2], bf[p][3],
                        Bbase + (wn + p * 16 + lr) * ROWB + (2 * s + lu) * 16);
#pragma unroll
            for (int mi = 0; mi < 4; mi++)
#pragma unroll
                for (int ni = 0; ni < 4; ni++) {
                    int p = ni >> 1, hi = ni & 1;
                    mma_bf16(acc[mi][ni][0], acc[mi][ni][1], acc[mi][ni][2], acc[mi][ni][3],
                             af[mi][0], af[mi][1], af[mi][2], af[mi][3],
                             bf[p][hi], bf[p][2 + hi]);
                }
        }
    }

    __syncthreads();
    float* ep = reinterpret_cast<float*>(smem);   // [128][132]
    const int er = lane >> 2;
    const int ec = (lane & 3) * 2;
#pragma unroll
    for (int mi = 0; mi < 4; mi++)
#pragma unroll
        for (int ni = 0; ni < 4; ni++) {
            int row = wm + mi * 16 + er;
            int col = wn + ni * 8 + ec;
            *reinterpret_cast<float2*>(ep + (size_t)row * 132 + col) =
                make_float2(acc[mi][ni][0], acc[mi][ni][1]);
            *reinterpret_cast<float2*>(ep + (size_t)(row + 8) * 132 + col) =
                make_float2(acc[mi][ni][2], acc[mi][ni][3]);
        }
    __syncthreads();

    {
        const int row  = tid >> 1;
        const int half = tid & 1;
        const int r    = Mt * 128 + row;
        float v[64];
        const float* rp = ep + (size_t)row * 132 + half * 64;
#pragma unroll
        for (int q = 0; q < 16; q++) {
            float4 f4 = *reinterpret_cast<const float4*>(rp + q * 4);
            v[q * 4 + 0] = f4.x; v[q * 4 + 1] = f4.y; v[q * 4 + 2] = f4.z; v[q * 4 + 3] = f4.w;
        }
        float m = -3.4e38f;
#pragma unroll
        for (int q = 0; q < 64; q++) m = fmaxf(m, v[q]);
        m = fmaxf(m, __shfl_xor_sync(0xffffffffu, m, 1));
        float s = 0.0f;
#pragma unroll
        for (int q = 0; q < 64; q++) { v[q] = exp2f((v[q] - m) * LOG2E_F); s += v[q]; }
        s += __shfl_xor_sync(0xffffffffu, s, 1);
        float inv = 1.0f / s;
        if (r < U) {
            union { __nv_fp8x2_storage_t h[32]; uint4 q4[4]; } pk;
#pragma unroll
            for (int q = 0; q < 32; q++)
                pk.h[q] = __nv_cvt_float2_to_fp8x2(
                    make_float2(v[2 * q] * inv, v[2 * q + 1] * inv),
                    __NV_SATFINITE, __NV_E4M3);
            uint4* op = reinterpret_cast<uint4*>(
                d_P8 + ((size_t)r * KC + iC) * KC + half * 64);
#pragma unroll
            for (int q = 0; q < 4; q++) op[q] = pk.q4[q];
        }
    }
    (void)dummy;
}

// =====================================================================
// Emission logits GEMM + partial lse (unchanged) + parallel final lse
// =====================================================================
__global__ void __launch_bounds__(256) k_emit_gemm(const float* __restrict__ emit_w,
                                                   const float* __restrict__ emb_cluster_w)
{
    const int vt = blockIdx.x;
    __shared__ float avs[16][65];
    __shared__ float bvs[16][129];
    __shared__ float pmS[8][128];
    __shared__ float psS[8][128];

    const int tid   = threadIdx.x;
    const int lane  = tid & 31;
    const int wg    = tid >> 5;
    const int rbase = wg * 8;
    const int cbase = lane * 4;

    float acc[8][4];
#pragma unroll
    for (int a = 0; a < 8; a++)
#pragma unroll
        for (int b = 0; b < 4; b++) acc[a][b] = 0.0f;

    for (int k0 = 0; k0 < KC; k0 += 16) {
#pragma unroll
        for (int it = 0; it < 4; it++) {
            int u = tid + it * 256;
            int kk = u & 15, row = u >> 4;
            avs[kk][row] = emit_w[(size_t)(vt * 64 + row) * KC + k0 + kk];
        }
#pragma unroll
        for (int it = 0; it < 8; it++) {
            int u = tid + it * 256;
            int kk = u & 15, c = u >> 4;
            bvs[kk][c] = emb_cluster_w[(size_t)c * KC + k0 + kk];
        }
        __syncthreads();
#pragma unroll
        for (int kk = 0; kk < 16; kk++) {
            float av[8], bv[4];
#pragma unroll
            for (int r2 = 0; r2 < 8; r2++) av[r2] = avs[kk][rbase + r2];
#pragma unroll
            for (int c2 = 0; c2 < 4; c2++) bv[c2] = bvs[kk][cbase + c2];
#pragma unroll
            for (int r2 = 0; r2 < 8; r2++)
#pragma unroll
                for (int c2 = 0; c2 < 4; c2++)
                    acc[r2][c2] = fmaf(av[r2], bv[c2], acc[r2][c2]);
        }
        __syncthreads();
    }

    float pm[4], ps[4];
#pragma unroll
    for (int c2 = 0; c2 < 4; c2++) { pm[c2] = -3.4e38f; ps[c2] = 0.0f; }
#pragma unroll
    for (int r2 = 0; r2 < 8; r2++) {
        int v = vt * 64 + rbase + r2;
        float4 f4 = make_float4(acc[r2][0], acc[r2][1], acc[r2][2], acc[r2][3]);
        *reinterpret_cast<float4*>(&d_LogitsT[(size_t)v * KC + cbase]) = f4;
#pragma unroll
        for (int c2 = 0; c2 < 4; c2++) pm[c2] = fmaxf(pm[c2], acc[r2][c2]);
    }
#pragma unroll
    for (int r2 = 0; r2 < 8; r2++)
#pragma unroll
        for (int c2 = 0; c2 < 4; c2++)
            ps[c2] += exp2f((acc[r2][c2] - pm[c2]) * LOG2E_F);

#pragma unroll
    for (int c2 = 0; c2 < 4; c2++) { pmS[wg][cbase + c2] = pm[c2]; psS[wg][cbase + c2] = ps[c2]; }
    __syncthreads();
    if (tid < 128) {
        float m = pmS[0][tid];
#pragma unroll
        for (int w = 1; w < 8; w++) m = fmaxf(m, pmS[w][tid]);
        float s = 0.0f;
#pragma unroll
        for (int w = 0; w < 8; w++) s += psS[w][tid] * exp2f((pmS[w][tid] - m) * LOG2E_F);
        d_PM[vt * KC + tid] = m;
        d_PS[vt * KC + tid] = s;
    }
}

// one block per cluster c; 256-thread strided reduction over 500 tiles
__global__ void __launch_bounds__(256) k_lse_final()
{
    __shared__ float sred[256];
    const int c   = blockIdx.x;
    const int tid = threadIdx.x;

    float m = -3.4e38f;
    for (int b = tid; b < VTILES; b += 256) m = fmaxf(m, d_PM[b * KC + c]);
    sred[tid] = m;
    __syncthreads();
    for (int o = 128; o; o >>= 1) {
        if (tid < o) sred[tid] = fmaxf(sred[tid], sred[tid + o]);
        __syncthreads();
    }
    float gm = sred[0];
    __syncthreads();

    float s = 0.0f;
    for (int b = tid; b < VTILES; b += 256)
        s += d_PS[b * KC + c] * exp2f((d_PM[b * KC + c] - gm) * LOG2E_F);
    sred[tid] = s;
    __syncthreads();
    for (int o = 128; o; o >>= 1) {
        if (tid < o) sred[tid] += sred[tid + o];
        __syncthreads();
    }
    if (tid == 0) d_RowLse[c] = gm + log2f(sred[0]) * LN2_F;
}

// =====================================================================
// Phase B: sequential scan, 3-stage cp.async pipeline (fp8 P + LogitsT)
// =====================================================================
constexpr int PBUF8     = KC * KC;               // 16384 bytes/stage
constexpr int EABUF     = KC * 4;                // 512
constexpr int SCAN_SMEM = 3 * (PBUF8 + EABUF);   // 50688

__global__ void __launch_bounds__(128) k_scan(const int* __restrict__ x,
                                              const float* __restrict__ start_w,
                                              const float* __restrict__ start_b)
{
    extern __shared__ __align__(16) char ps[];
    __shared__ float w_s[128];
    __shared__ float red[4][132];
    __shared__ float smax[4], ssum[4];

    const int n    = blockIdx.x;
    const int tid  = threadIdx.x;
    const int lane = tid & 31;
    const int wid  = tid >> 5;
    const int jg   = lane;
    const int ic   = wid;
    const uint32_t sbase  = smem_u32(ps);
    const uint32_t eabase = sbase + 3 * PBUF8;
    const float rl = d_RowLse[tid];

    auto prefetch = [&](int t) {
        const int r = t * NB + n;
        const int slot = d_RowSlot[r];
        const char* gp = reinterpret_cast<const char*>(d_P8 + (size_t)slot * KC * KC);
        uint32_t dst = sbase + (t % 3) * PBUF8;
#pragma unroll
        for (int k = 0; k < 8; k++) {
            int idx = tid + k * 128;
            cpa16(dst + idx * 16, gp + idx * 16);
        }
        const int w = x[n * TT + t + 1];
        cpa4(eabase + (t % 3) * EABUF + tid * 4, d_LogitsT + (size_t)w * KC + tid);
    };

    prefetch(0);
    asm volatile("cp.async.commit_group;" ::: "memory");
    prefetch(1);
    asm volatile("cp.async.commit_group;" ::: "memory");

    float a0 = start_w[tid] + start_b[tid];
    float m = warpMax(a0);
    if (lane == 0) smax[wid] = m;
    __syncthreads();
    m = fmaxf(fmaxf(smax[0], smax[1]), fmaxf(smax[2], smax[3]));
    float e = exp2f((a0 - m) * LOG2E_F);
    float s = warpSum(e);
    if (lane == 0) ssum[wid] = s;
    __syncthreads();
    s = ssum[0] + ssum[1] + ssum[2] + ssum[3];
    float alpha = a0 - m - log2f(s) * LN2_F;
    __syncthreads();

    for (int t = 0; t < TT - 1; t++) {
        if (t + 2 < TT - 1) prefetch(t + 2);
        asm volatile("cp.async.commit_group;" ::: "memory");

        float mm = warpMax(alpha);
        if (lane == 0) smax[wid] = mm;
        __syncthreads();
        mm = fmaxf(fmaxf(smax[0], smax[1]), fmaxf(smax[2], smax[3]));
        w_s[tid] = exp2f((alpha - mm) * LOG2E_F);
        asm volatile("cp.async.wait_group %0;" :: "n"(2) : "memory");
        __syncthreads();

        const size_t off = (size_t)(t % 3) * PBUF8;
        float acc0 = 0.f, acc1 = 0.f, acc2 = 0.f, acc3 = 0.f;
#pragma unroll
        for (int ii = 0; ii < 32; ii++) {
            const int i = ic * 32 + ii;
            uint32_t u = *reinterpret_cast<const uint32_t*>(ps + off + i * 128 + jg * 4);
            float wi = w_s[i];
            __half2_raw r01 = __nv_cvt_fp8x2_to_halfraw2(
                (__nv_fp8x2_storage_t)(u & 0xffffu), __NV_E4M3);
            __half2_raw r23 = __nv_cvt_fp8x2_to_halfraw2(
                (__nv_fp8x2_storage_t)(u >> 16), __NV_E4M3);
            float2 f01 = __half22float2(*reinterpret_cast<__half2*>(&r01));
            float2 f23 = __half22float2(*reinterpret_cast<__half2*>(&r23));
            acc0 = fmaf(wi, f01.x, acc0);
            acc1 = fmaf(wi, f01.y, acc1);
            acc2 = fmaf(wi, f23.x, acc2);
            acc3 = fmaf(wi, f23.y, acc3);
        }
        red[ic][jg * 4 + 0] = acc0;
        red[ic][jg * 4 + 1] = acc1;
        red[ic][jg * 4 + 2] = acc2;
        red[ic][jg * 4 + 3] = acc3;
        __syncthreads();
        float tot = red[0][tid] + red[1][tid] + red[2][tid] + red[3][tid];
        float ea = *reinterpret_cast<const float*>(ps + 3 * PBUF8 + (t % 3) * EABUF + tid * 4);
        alpha = mm + log2f(tot) * LN2_F + (ea - rl);
        __syncthreads();
    }

    float mm = warpMax(alpha);
    if (lane == 0) smax[wid] = mm;
    __syncthreads();
    mm = fmaxf(fmaxf(smax[0], smax[1]), fmaxf(smax[2], smax[3]));
    float ee = exp2f((alpha - mm) * LOG2E_F);
    float ss = warpSum(ee);
    if (lane == 0) ssum[wid] = ss;
    __syncthreads();
    if (tid == 0) {
        float stot = ssum[0] + ssum[1] + ssum[2] + ssum[3];
        d_Chain[n] = mm + log2f(stot) * LN2_F;
    }
}

__global__ void k_final(float* out, int out_size)
{
    __shared__ float sh;
    if (threadIdx.x == 0) {
        float s = 0.0f;
        for (int i = 0; i < NB; i++) s += d_Chain[i];
        sh = -s / (float)NB;
    }
    __syncthreads();
    for (int i = threadIdx.x; i < out_size; i += blockDim.x) out[i] = sh;
}

extern "C" void kernel_launch(void* const* d_in, const int* in_sizes, int n_in,
                              void* d_out, int out_size)
{
    (void)in_sizes; (void)n_in;
    const int*   x             = (const int*)d_in[0];
    const float* embed_w       = (const float*)d_in[1];
    const float* trans_w       = (const float*)d_in[2];
    const float* start_w       = (const float*)d_in[3];
    const float* start_b       = (const float*)d_in[4];
    const float* emb_cluster_w = (const float*)d_in[5];
    const float* emit_w        = (const float*)d_in[6];

    cudaFuncSetAttribute(k_mma, cudaFuncAttributeMaxDynamicSharedMemorySize, SMEM_MMA);
    cudaFuncSetAttribute(k_scan, cudaFuncAttributeMaxDynamicSharedMemorySize, SCAN_SMEM);

    k_zero<<<(VV + 255) / 256, 256>>>();
    k_mark<<<(RR + 255) / 256, 256>>>(x);
    k_slot<<<1, 1024>>>();
    k_rowslot<<<(RR + 255) / 256, 256>>>(x);
    k_prepB<<<4096, 256>>>(trans_w);
    k_prepA<<<RPAD, 64>>>(embed_w);
    k_emit_gemm<<<VTILES, 256>>>(emit_w, emb_cluster_w);
    k_lse_final<<<KC, 256>>>();
    k_mma<<<dim3(128, 128), 256, SMEM_MMA>>>(0);
    k_scan<<<NB, 128, SCAN_SMEM>>>(x, start_w, start_b);
    k_final<<<1, 64>>>((float*)d_out, out_size);
}